// round 6
// baseline (speedup 1.0000x reference)
#include <cuda_runtime.h>
#include <cuda_bf16.h>
#include <math.h>

// Fixed shapes
#define B_ 32
#define C_ 6
#define T_ 64
#define K_ 8
#define N_ 128
#define NSEG 1016
#define NSEGP 1024
#define NCL 2048
#define NCLP2 1024             // candidate pairs
#define EPS_ 1e-6f
#define THRESH_ 0.5f

#define THREADS 256
#define GL 64                  // lanes per point-group (2 warps)
#define NG 4                   // groups per block
#define M 4                    // points per group
#define PTS_BLK (NG * M)       // 16
#define NCHUNK (T_ / PTS_BLK)  // 4
// grid = B*C*NCHUNK = 768

typedef unsigned long long u64;

__device__ __forceinline__ u64 F2ADD(u64 a, u64 b) {
    u64 d; asm("add.rn.f32x2 %0,%1,%2;" : "=l"(d) : "l"(a), "l"(b)); return d;
}
__device__ __forceinline__ u64 F2SUB(u64 a, u64 b) {
    u64 d; asm("sub.rn.f32x2 %0,%1,%2;" : "=l"(d) : "l"(a), "l"(b)); return d;
}
__device__ __forceinline__ u64 F2MUL(u64 a, u64 b) {
    u64 d; asm("mul.rn.f32x2 %0,%1,%2;" : "=l"(d) : "l"(a), "l"(b)); return d;
}
__device__ __forceinline__ u64 F2FMA(u64 a, u64 b, u64 c) {
    u64 d; asm("fma.rn.f32x2 %0,%1,%2,%3;" : "=l"(d) : "l"(a), "l"(b), "l"(c)); return d;
}
__device__ __forceinline__ u64 F2PK(float lo, float hi) {
    u64 d; asm("mov.b64 %0,{%1,%2};" : "=l"(d) : "f"(lo), "f"(hi)); return d;
}
__device__ __forceinline__ void F2UP(u64 a, float& lo, float& hi) {
    asm("mov.b64 {%0,%1},%2;" : "=f"(lo), "=f"(hi) : "l"(a));
}
__device__ __forceinline__ float frcp(float x) {
    float r; asm("rcp.approx.f32 %0,%1;" : "=f"(r) : "f"(x)); return r;
}

__global__ void offroad_init_kernel(float* out) {
    int i = threadIdx.x;
    if (i < B_ * C_) out[i] = 0.0f;
}

__global__ __launch_bounds__(THREADS, 4)
void offroad_kernel(const float* __restrict__ points,
                    const float* __restrict__ road_boundary,
                    const float* __restrict__ centerlines,
                    float* __restrict__ out) {
    __shared__ float4 sA[NSEGP];     // (-ax,-ax,-ay,-ay)
    __shared__ float4 sD[NSEGP];     // (-dx,-dx,-dy,-dy)
    __shared__ float4 sCl[NCLP2];    // (-qx0,-qx1,-qy0,-qy1) per cand pair
    __shared__ float2 sRedA[NG][2][M];
    __shared__ float2 sRedB[NG][2][M];
    __shared__ float  sTerm[PTS_BLK];

    const int bid = blockIdx.x;
    const int chunk = bid & (NCHUNK - 1);
    const int c = (bid >> 2) % C_;
    const int b = bid / (NCHUNK * C_);
    const int tid = threadIdx.x;

    // ---- fill segments ----
    {
        const float2* rb = (const float2*)road_boundary + (size_t)b * K_ * N_;
        #pragma unroll
        for (int s0 = 0; s0 < NSEGP; s0 += THREADS) {
            int s = s0 + tid;
            float nax, nay, ndx, ndy;
            if (s < NSEG) {
                int k = s / (N_ - 1);
                int j = s - k * (N_ - 1);
                float2 a = rb[k * N_ + j];
                float2 e = rb[k * N_ + j + 1];
                nax = -a.x; nay = -a.y;
                ndx = a.x - e.x; ndy = a.y - e.y;
            } else {
                nax = -1e19f; nay = -1e19f; ndx = 0.0f; ndy = 0.0f;
            }
            sA[s] = make_float4(nax, nax, nay, nay);
            sD[s] = make_float4(ndx, ndx, ndy, ndy);
        }
    }
    // ---- fill centerlines (negated, pair-SoA) ----
    {
        const float4* cl4 = (const float4*)(centerlines + (size_t)b * NCL * 2);
        #pragma unroll
        for (int p0 = 0; p0 < NCLP2; p0 += THREADS) {
            int pi = p0 + tid;
            float4 v = cl4[pi];     // (q0x,q0y,q1x,q1y)
            sCl[pi] = make_float4(-v.x, -v.z, -v.y, -v.w);
        }
    }
    __syncthreads();

    const int grp = tid >> 6;        // 0..3
    const int wig = (tid >> 5) & 1;  // warp in group
    const int lG  = tid & 63;        // lane in group

    float px[M], py[M];
    {
        const float2* pp = (const float2*)points +
            ((size_t)(b * C_ + c)) * T_ + chunk * PTS_BLK + grp * M;
        #pragma unroll
        for (int j = 0; j < M; j++) { float2 p = pp[j]; px[j] = p.x; py[j] = p.y; }
    }

    // ---- Phase A: argmin over candidates (packed over cand pairs) ----
    u64 pxd[M], pyd[M];
    #pragma unroll
    for (int j = 0; j < M; j++) { pxd[j] = F2PK(px[j], px[j]); pyd[j] = F2PK(py[j], py[j]); }

    float sc[M]; int bi[M];
    #pragma unroll
    for (int j = 0; j < M; j++) { sc[j] = 3.4e38f; bi[j] = 0; }

    #pragma unroll 4
    for (int it = 0; it < NCLP2 / GL; it++) {       // 16 iters
        int pi = lG + it * GL;
        float4 nq = sCl[pi];
        u64 nqx = F2PK(nq.x, nq.y);
        u64 nqy = F2PK(nq.z, nq.w);
        int c0 = 2 * pi;
        #pragma unroll
        for (int j = 0; j < M; j++) {
            u64 ax = F2ADD(pxd[j], nqx);            // px - qx (pair)
            u64 ay = F2ADD(pyd[j], nqy);
            u64 d2 = F2FMA(ay, ay, F2MUL(ax, ax));
            float d20, d21; F2UP(d2, d20, d21);
            float pmin = fminf(d20, d21);
            int   pidx = c0 + ((d21 < d20) ? 1 : 0);
            if (pmin < sc[j]) { sc[j] = pmin; bi[j] = pidx; }
        }
    }
    #pragma unroll
    for (int off = 16; off; off >>= 1) {
        #pragma unroll
        for (int j = 0; j < M; j++) {
            float os = __shfl_xor_sync(0xffffffffu, sc[j], off);
            int   oi = __shfl_xor_sync(0xffffffffu, bi[j], off);
            if (os < sc[j] || (os == sc[j] && oi < bi[j])) { sc[j] = os; bi[j] = oi; }
        }
    }
    if ((tid & 31) == 0) {
        #pragma unroll
        for (int j = 0; j < M; j++)
            sRedA[grp][wig][j] = make_float2(sc[j], __int_as_float(bi[j]));
    }
    __syncthreads();
    // combine the group's 2 warps (broadcast reads)
    #pragma unroll
    for (int j = 0; j < M; j++) {
        float2 e0 = sRedA[grp][0][j];
        float2 e1 = sRedA[grp][1][j];
        int i0 = __float_as_int(e0.y), i1 = __float_as_int(e1.y);
        bi[j] = (e1.x < e0.x || (e1.x == e0.x && i1 < i0)) ? i1 : i0;
    }

    // per-pair packed constants
    float dax[M], day[M];
    const float* clf = (const float*)sCl;
    #pragma unroll
    for (int j = 0; j < M; j++) {
        int p_ = bi[j] >> 1, h_ = bi[j] & 1;
        float nqx = clf[p_ * 4 + h_];
        float nqy = clf[p_ * 4 + 2 + h_];
        dax[j] = -nqx - px[j];     // qx - px
        day[j] = -nqy - py[j];
    }
    u64 px2[2]   = { F2PK(px[0], px[1]),   F2PK(px[2], px[3]) };
    u64 py2[2]   = { F2PK(py[0], py[1]),   F2PK(py[2], py[3]) };
    u64 dax2[2]  = { F2PK(dax[0], dax[1]), F2PK(dax[2], dax[3]) };
    u64 nday2[2] = { F2PK(-day[0], -day[1]), F2PK(-day[2], -day[3]) };
    const u64 neps2 = F2PK(-EPS_, -EPS_);

    // ---- Phase B: fused distance + intersection over segments ----
    float mind2[M], hAcc[M];
    #pragma unroll
    for (int j = 0; j < M; j++) { mind2[j] = 3.4e38f; hAcc[j] = 3.4e38f; }

    #pragma unroll 4
    for (int it = 0; it < NSEGP / GL; it++) {       // 16 iters
        int s = lG + it * GL;
        float4 A = sA[s];
        float4 D = sD[s];
        u64 nax2 = F2PK(A.x, A.y), nay2 = F2PK(A.z, A.w);
        u64 ndx2 = F2PK(D.x, D.y), ndy2 = F2PK(D.z, D.w);
        float len2 = fmaf(D.x, D.x, fmaf(D.z, D.z, EPS_));
        float r = frcp(len2);
        u64 ninv2 = F2PK(-r, -r);
        #pragma unroll
        for (int q = 0; q < 2; q++) {
            int j0 = 2 * q, j1 = 2 * q + 1;
            u64 v1x = F2ADD(px2[q], nax2);          // p - a
            u64 v1y = F2ADD(py2[q], nay2);
            u64 ndt = F2FMA(v1y, ndy2, F2MUL(v1x, ndx2));   // -(v1.d)
            u64 pr  = F2MUL(ndt, ninv2);            // dot/(len2+eps)
            float p0, p1; F2UP(pr, p0, p1);
            p0 = __saturatef(p0); p1 = __saturatef(p1);
            pr = F2PK(p0, p1);
            u64 ex = F2FMA(ndx2, pr, v1x);          // v1x - dx*pr
            u64 ey = F2FMA(ndy2, pr, v1y);
            u64 d2 = F2FMA(ey, ey, F2MUL(ex, ex));
            float d20, d21; F2UP(d2, d20, d21);
            mind2[j0] = fminf(mind2[j0], d20);
            mind2[j1] = fminf(mind2[j1], d21);
            // nw = -(cross(da,db)+eps);  c1 = cross(da,v1);  c2 = cross(db,v1)
            u64 nw = F2FMA(nday2[q], ndx2, F2FMA(dax2[q], ndy2, neps2));
            u64 c1 = F2FMA(dax2[q], v1y, F2MUL(nday2[q], v1x));
            u64 c2 = F2SUB(F2MUL(ndy2, v1x), F2MUL(ndx2, v1y));
            u64 s1 = F2MUL(c1, F2ADD(c1, nw));      // c1*(c1-w)
            u64 s2 = F2MUL(c2, F2ADD(c2, nw));      // c2*(c2-w)
            float s10, s11, s20, s21;
            F2UP(s1, s10, s11); F2UP(s2, s20, s21);
            hAcc[j0] = fminf(hAcc[j0], fmaxf(s10, s20));   // hit iff <= 0
            hAcc[j1] = fminf(hAcc[j1], fmaxf(s11, s21));
        }
    }
    #pragma unroll
    for (int off = 16; off; off >>= 1) {
        #pragma unroll
        for (int j = 0; j < M; j++) {
            mind2[j] = fminf(mind2[j], __shfl_xor_sync(0xffffffffu, mind2[j], off));
            hAcc[j]  = fminf(hAcc[j],  __shfl_xor_sync(0xffffffffu, hAcc[j], off));
        }
    }
    if ((tid & 31) == 0) {
        #pragma unroll
        for (int j = 0; j < M; j++)
            sRedB[grp][wig][j] = make_float2(mind2[j], hAcc[j]);
    }
    __syncthreads();

    if (tid < PTS_BLK) {
        int g_ = tid >> 2, j_ = tid & 3;
        float2 e0 = sRedB[g_][0][j_];
        float2 e1 = sRedB[g_][1][j_];
        float md2 = fminf(e0.x, e1.x);
        float ha  = fminf(e0.y, e1.y);
        float md = sqrtf(md2);
        md = (ha <= 0.0f) ? md : -md;      // intersection -> outside (+), else inside (-)
        sTerm[tid] = fmaxf(md + THRESH_, 0.0f);
    }
    __syncthreads();
    if (tid == 0) {
        float ssum = 0.0f;
        #pragma unroll
        for (int i = 0; i < PTS_BLK; i++) ssum += sTerm[i];
        atomicAdd(&out[b * C_ + c], ssum);
    }
}

extern "C" void kernel_launch(void* const* d_in, const int* in_sizes, int n_in,
                              void* d_out, int out_size) {
    const float* points      = (const float*)d_in[0];
    const float* road_bound  = (const float*)d_in[1];
    const float* centerlines = (const float*)d_in[2];
    float* out = (float*)d_out;
    (void)in_sizes; (void)n_in; (void)out_size;

    offroad_init_kernel<<<1, 256>>>(out);
    offroad_kernel<<<B_ * C_ * NCHUNK, THREADS>>>(points, road_bound, centerlines, out);
}

// round 7
// speedup vs baseline: 1.0993x; 1.0993x over previous
#include <cuda_runtime.h>
#include <cuda_bf16.h>
#include <math.h>

// Fixed shapes
#define B_ 32
#define C_ 6
#define T_ 64
#define K_ 8
#define N_ 128
#define NSEG 1016
#define NSEGP 1024
#define NCL 2048
#define NCLP2 1024             // candidate pairs
#define EPS_ 1e-6f
#define THRESH_ 0.5f

#define THREADS 512
#define GL 64                  // lanes per point-group (2 warps)
#define NG 8                   // groups per block
#define M 4                    // points per group
#define PTS_BLK (NG * M)       // 32
#define HALVES (T_ / PTS_BLK)  // 2
// grid = B*C*HALVES = 384

typedef unsigned long long u64;

__device__ __forceinline__ u64 F2ADD(u64 a, u64 b) {
    u64 d; asm("add.rn.f32x2 %0,%1,%2;" : "=l"(d) : "l"(a), "l"(b)); return d;
}
__device__ __forceinline__ u64 F2SUB(u64 a, u64 b) {
    u64 d; asm("sub.rn.f32x2 %0,%1,%2;" : "=l"(d) : "l"(a), "l"(b)); return d;
}
__device__ __forceinline__ u64 F2MUL(u64 a, u64 b) {
    u64 d; asm("mul.rn.f32x2 %0,%1,%2;" : "=l"(d) : "l"(a), "l"(b)); return d;
}
__device__ __forceinline__ u64 F2FMA(u64 a, u64 b, u64 c) {
    u64 d; asm("fma.rn.f32x2 %0,%1,%2,%3;" : "=l"(d) : "l"(a), "l"(b), "l"(c)); return d;
}
__device__ __forceinline__ u64 F2PK(float lo, float hi) {
    u64 d; asm("mov.b64 %0,{%1,%2};" : "=l"(d) : "f"(lo), "f"(hi)); return d;
}
__device__ __forceinline__ void F2UP(u64 a, float& lo, float& hi) {
    asm("mov.b64 {%0,%1},%2;" : "=f"(lo), "=f"(hi) : "l"(a));
}
__device__ __forceinline__ float frcp(float x) {
    float r; asm("rcp.approx.f32 %0,%1;" : "=f"(r) : "f"(x)); return r;
}

__global__ void offroad_init_kernel(float* out) {
    int i = threadIdx.x;
    if (i < B_ * C_) out[i] = 0.0f;
}

__global__ __launch_bounds__(THREADS, 2)
void offroad_kernel(const float* __restrict__ points,
                    const float* __restrict__ road_boundary,
                    const float* __restrict__ centerlines,
                    float* __restrict__ out) {
    __shared__ float4 sA[NSEGP];     // (-ax,-ax,-ay,-ay)
    __shared__ float4 sD[NSEGP];     // (-dx,-dx,-dy,-dy)
    __shared__ float4 sCl[NCLP2];    // (-qx0,-qx1,-qy0,-qy1) per cand pair
    __shared__ float2 sClh[NCLP2];   // (h0,h1) = 0.5*|q|^2 per pair
    __shared__ float2 sRedA[NG][2][M];
    __shared__ float2 sRedB[NG][2][M];

    const int bid = blockIdx.x;
    const int half = bid & 1;
    const int c = (bid >> 1) % C_;
    const int b = bid / (2 * C_);
    const int tid = threadIdx.x;

    // ---- fill segments ----
    {
        const float2* rb = (const float2*)road_boundary + (size_t)b * K_ * N_;
        #pragma unroll
        for (int s0 = 0; s0 < NSEGP; s0 += THREADS) {
            int s = s0 + tid;
            float nax, nay, ndx, ndy;
            if (s < NSEG) {
                int k = s / (N_ - 1);
                int j = s - k * (N_ - 1);
                float2 a = rb[k * N_ + j];
                float2 e = rb[k * N_ + j + 1];
                nax = -a.x; nay = -a.y;
                ndx = a.x - e.x; ndy = a.y - e.y;
            } else {
                nax = -1e19f; nay = -1e19f; ndx = 0.0f; ndy = 0.0f;
            }
            sA[s] = make_float4(nax, nax, nay, nay);
            sD[s] = make_float4(ndx, ndx, ndy, ndy);
        }
    }
    // ---- fill centerlines (negated pair-SoA + half-norms) ----
    {
        const float4* cl4 = (const float4*)(centerlines + (size_t)b * NCL * 2);
        #pragma unroll
        for (int p0 = 0; p0 < NCLP2; p0 += THREADS) {
            int pi = p0 + tid;
            float4 v = cl4[pi];     // (q0x,q0y,q1x,q1y)
            sCl[pi] = make_float4(-v.x, -v.z, -v.y, -v.w);
            sClh[pi] = make_float2(0.5f * fmaf(v.x, v.x, v.y * v.y),
                                   0.5f * fmaf(v.z, v.z, v.w * v.w));
        }
    }
    __syncthreads();

    const int grp = tid >> 6;        // 0..7
    const int wig = (tid >> 5) & 1;  // warp in group
    const int lG  = tid & 63;        // lane in group

    float px[M], py[M];
    {
        const float2* pp = (const float2*)points +
            ((size_t)(b * C_ + c)) * T_ + half * PTS_BLK + grp * M;
        #pragma unroll
        for (int j = 0; j < M; j++) { float2 p = pp[j]; px[j] = p.x; py[j] = p.y; }
    }

    // ---- Phase A: argmin over candidates (score = 0.5|q|^2 - p.q, packed pairs) ----
    u64 pxd[M], pyd[M];
    #pragma unroll
    for (int j = 0; j < M; j++) { pxd[j] = F2PK(px[j], px[j]); pyd[j] = F2PK(py[j], py[j]); }

    float sc[M]; int bi[M];
    #pragma unroll
    for (int j = 0; j < M; j++) { sc[j] = 3.4e38f; bi[j] = 0; }

    const u64* clh64 = (const u64*)sClh;
    #pragma unroll 4
    for (int it = 0; it < NCLP2 / GL; it++) {       // 16 iters
        int pi = lG + it * GL;
        float4 nq = sCl[pi];
        u64 h2  = clh64[pi];
        u64 nqx = F2PK(nq.x, nq.y);
        u64 nqy = F2PK(nq.z, nq.w);
        int c0 = 2 * pi;
        #pragma unroll
        for (int j = 0; j < M; j++) {
            u64 s2 = F2FMA(pxd[j], nqx, F2FMA(pyd[j], nqy, h2));
            float s0, s1; F2UP(s2, s0, s1);
            float pmin = fminf(s0, s1);
            int   pidx = c0 + ((s1 < s0) ? 1 : 0);
            if (pmin < sc[j]) { sc[j] = pmin; bi[j] = pidx; }
        }
    }
    #pragma unroll
    for (int off = 16; off; off >>= 1) {
        #pragma unroll
        for (int j = 0; j < M; j++) {
            float os = __shfl_xor_sync(0xffffffffu, sc[j], off);
            int   oi = __shfl_xor_sync(0xffffffffu, bi[j], off);
            if (os < sc[j] || (os == sc[j] && oi < bi[j])) { sc[j] = os; bi[j] = oi; }
        }
    }
    if ((tid & 31) == 0) {
        #pragma unroll
        for (int j = 0; j < M; j++)
            sRedA[grp][wig][j] = make_float2(sc[j], __int_as_float(bi[j]));
    }
    __syncthreads();
    #pragma unroll
    for (int j = 0; j < M; j++) {
        float2 e0 = sRedA[grp][0][j];
        float2 e1 = sRedA[grp][1][j];
        int i0 = __float_as_int(e0.y), i1 = __float_as_int(e1.y);
        bi[j] = (e1.x < e0.x || (e1.x == e0.x && i1 < i0)) ? i1 : i0;
    }

    // per-pair packed constants
    float dax[M], day[M];
    const float* clf = (const float*)sCl;
    #pragma unroll
    for (int j = 0; j < M; j++) {
        int p_ = bi[j] >> 1, h_ = bi[j] & 1;
        float nqx = clf[p_ * 4 + h_];
        float nqy = clf[p_ * 4 + 2 + h_];
        dax[j] = -nqx - px[j];     // qx - px
        day[j] = -nqy - py[j];
    }
    u64 px2[2]   = { F2PK(px[0], px[1]),   F2PK(px[2], px[3]) };
    u64 py2[2]   = { F2PK(py[0], py[1]),   F2PK(py[2], py[3]) };
    u64 dax2[2]  = { F2PK(dax[0], dax[1]), F2PK(dax[2], dax[3]) };
    u64 nday2[2] = { F2PK(-day[0], -day[1]), F2PK(-day[2], -day[3]) };
    const u64 neps2 = F2PK(-EPS_, -EPS_);

    // ---- Phase B: fused distance + intersection over segments ----
    float mind2[M], hAcc[M];
    #pragma unroll
    for (int j = 0; j < M; j++) { mind2[j] = 3.4e38f; hAcc[j] = 3.4e38f; }

    #pragma unroll 4
    for (int it = 0; it < NSEGP / GL; it++) {       // 16 iters
        int s = lG + it * GL;
        float4 A = sA[s];
        float4 D = sD[s];
        u64 nax2 = F2PK(A.x, A.y), nay2 = F2PK(A.z, A.w);
        u64 ndx2 = F2PK(D.x, D.y), ndy2 = F2PK(D.z, D.w);
        float len2 = fmaf(D.x, D.x, fmaf(D.z, D.z, EPS_));
        float r = frcp(len2);
        u64 ninv2 = F2PK(-r, -r);
        #pragma unroll
        for (int q = 0; q < 2; q++) {
            int j0 = 2 * q, j1 = 2 * q + 1;
            u64 v1x = F2ADD(px2[q], nax2);          // p - a
            u64 v1y = F2ADD(py2[q], nay2);
            u64 ndt = F2FMA(v1y, ndy2, F2MUL(v1x, ndx2));   // -(v1.d)
            u64 pr  = F2MUL(ndt, ninv2);            // dot/(len2+eps)
            float p0, p1; F2UP(pr, p0, p1);
            p0 = __saturatef(p0); p1 = __saturatef(p1);
            pr = F2PK(p0, p1);
            u64 ex = F2FMA(ndx2, pr, v1x);          // v1x - dx*pr
            u64 ey = F2FMA(ndy2, pr, v1y);
            u64 d2 = F2FMA(ey, ey, F2MUL(ex, ex));
            float d20, d21; F2UP(d2, d20, d21);
            mind2[j0] = fminf(mind2[j0], d20);
            mind2[j1] = fminf(mind2[j1], d21);
            // nw = -(cross(da,db)+eps); c1 = cross(da,v1); c2 = cross(db,v1)
            u64 nw = F2FMA(nday2[q], ndx2, F2FMA(dax2[q], ndy2, neps2));
            u64 c1 = F2FMA(dax2[q], v1y, F2MUL(nday2[q], v1x));
            u64 c2 = F2SUB(F2MUL(ndy2, v1x), F2MUL(ndx2, v1y));
            u64 s1 = F2MUL(c1, F2ADD(c1, nw));      // c1*(c1-w)
            u64 s2 = F2MUL(c2, F2ADD(c2, nw));      // c2*(c2-w)
            float s10, s11, s20, s21;
            F2UP(s1, s10, s11); F2UP(s2, s20, s21);
            hAcc[j0] = fminf(hAcc[j0], fmaxf(s10, s20));   // hit iff <= 0
            hAcc[j1] = fminf(hAcc[j1], fmaxf(s11, s21));
        }
    }
    #pragma unroll
    for (int off = 16; off; off >>= 1) {
        #pragma unroll
        for (int j = 0; j < M; j++) {
            mind2[j] = fminf(mind2[j], __shfl_xor_sync(0xffffffffu, mind2[j], off));
            hAcc[j]  = fminf(hAcc[j],  __shfl_xor_sync(0xffffffffu, hAcc[j], off));
        }
    }
    if ((tid & 31) == 0) {
        #pragma unroll
        for (int j = 0; j < M; j++)
            sRedB[grp][wig][j] = make_float2(mind2[j], hAcc[j]);
    }
    __syncthreads();

    // warp 0: one thread per point (32 points), reduce and accumulate
    if (tid < 32) {
        int g_ = tid >> 2, j_ = tid & 3;
        float2 e0 = sRedB[g_][0][j_];
        float2 e1 = sRedB[g_][1][j_];
        float md2 = fminf(e0.x, e1.x);
        float ha  = fminf(e0.y, e1.y);
        float md = sqrtf(md2);
        md = (ha <= 0.0f) ? md : -md;      // intersection -> outside (+), else inside (-)
        float term = fmaxf(md + THRESH_, 0.0f);
        #pragma unroll
        for (int off = 16; off; off >>= 1)
            term += __shfl_xor_sync(0xffffffffu, term, off);
        if (tid == 0) atomicAdd(&out[b * C_ + c], term);
    }
}

extern "C" void kernel_launch(void* const* d_in, const int* in_sizes, int n_in,
                              void* d_out, int out_size) {
    const float* points      = (const float*)d_in[0];
    const float* road_bound  = (const float*)d_in[1];
    const float* centerlines = (const float*)d_in[2];
    float* out = (float*)d_out;
    (void)in_sizes; (void)n_in; (void)out_size;

    offroad_init_kernel<<<1, 256>>>(out);
    offroad_kernel<<<B_ * C_ * HALVES, THREADS>>>(points, road_bound, centerlines, out);
}